// round 14
// baseline (speedup 1.0000x reference)
#include <cuda_runtime.h>
#include <cuda_fp16.h>
#include <cstdint>
#include <cstddef>

#define IMG_B   64
#define IMG_H   32
#define IMG_W   4096
#define NSLICE  512
#define MTOT    32768
#define KTOT    1024
#define NTOT    512

// Tiled + pre-swizzled operand storage.
//   g_A: [m_tile 0..255][kc 0..15][row 0..127][16B chunk, ch^(row&7)]  64 MB
//   g_W: [bx 0..1][kc 0..15][row 0..255][16B chunk, ch^(row&7)]        1 MB
__device__ __align__(128) __half g_A[(size_t)MTOT * KTOT];
__device__ __align__(128) __half g_W[(size_t)NTOT * KTOT];

// ---------------------------------------------------------------------------
// helpers
// ---------------------------------------------------------------------------
__device__ __forceinline__ uint32_t smem_u32(const void* p) {
    uint32_t a;
    asm("{ .reg .u64 t; cvta.to.shared.u64 t, %1; cvt.u32.u64 %0, t; }" : "=r"(a) : "l"(p));
    return a;
}

__device__ __forceinline__ void ldsm_x4(uint32_t r[4], uint32_t addr) {
    asm volatile("ldmatrix.sync.aligned.m8n8.x4.shared.b16 {%0,%1,%2,%3}, [%4];"
                 : "=r"(r[0]), "=r"(r[1]), "=r"(r[2]), "=r"(r[3]) : "r"(addr));
}

__device__ __forceinline__ void mma_f16(float c[4], const uint32_t a[4],
                                        uint32_t b0, uint32_t b1) {
    asm volatile(
        "mma.sync.aligned.m16n8k16.row.col.f32.f16.f16.f32 "
        "{%0,%1,%2,%3}, {%4,%5,%6,%7}, {%8,%9}, {%0,%1,%2,%3};"
        : "+f"(c[0]), "+f"(c[1]), "+f"(c[2]), "+f"(c[3])
        : "r"(a[0]), "r"(a[1]), "r"(a[2]), "r"(a[3]), "r"(b0), "r"(b1));
}

__device__ __forceinline__ void bulk_g2s(uint32_t sdst, const void* gsrc,
                                         uint32_t bytes, uint32_t mbar) {
    asm volatile(
        "cp.async.bulk.shared::cluster.global.mbarrier::complete_tx::bytes "
        "[%0], [%1], %2, [%3];"
        :: "r"(sdst), "l"(gsrc), "r"(bytes), "r"(mbar) : "memory");
}

#define MBARRIER_INIT(a, c) \
    asm volatile("mbarrier.init.shared.b64 [%0], %1;" :: "r"((uint32_t)(a)), "r"((uint32_t)(c)) : "memory")
#define MBARRIER_EXPECT_TX(a, b) \
    asm volatile("mbarrier.arrive.expect_tx.shared.b64 _, [%0], %1;" :: "r"((uint32_t)(a)), "r"((uint32_t)(b)) : "memory")

#define MBARRIER_WAIT_PARITY(mbar_addr, parity) do { \
    uint32_t _mbar = (uint32_t)(mbar_addr); \
    uint32_t _par  = (uint32_t)(parity); \
    uint32_t _done_; \
    asm volatile("{\n\t.reg .pred p;\n\t" \
        "mbarrier.try_wait.parity.acquire.cta.shared::cta.b64 p, [%1], %2;\n\t" \
        "selp.b32 %0, 1, 0, p;\n\t}" \
        : "=r"(_done_) : "r"(_mbar), "r"(_par) : "memory"); \
    if (!_done_) { \
        asm volatile("{\n\t.reg .pred P1;\n\t" \
            "WAIT_LOOP_%=:\n\t" \
            "mbarrier.try_wait.parity.acquire.cta.shared::cta.b64 P1, [%0], %1, 0x989680;\n\t" \
            "@P1 bra.uni WAIT_DONE_%=;\n\t" \
            "bra.uni WAIT_LOOP_%=;\n\t" \
            "WAIT_DONE_%=:\n\t}" \
            :: "r"(_mbar), "r"(_par) : "memory"); \
    } \
} while (0)

// ---------------------------------------------------------------------------
// Kernel 1 (abuild v3, verbatim): 2 h-rows per block, 512 threads.
// Grid (2 halves, 16 h-pairs, 64 b).
// ---------------------------------------------------------------------------
#define SPAN    2088            // padded strip length (522 float4)
#define NGRP    519             // groups of 4 F outputs per h row
#define FSSZ    2336            // >= FIDX(2075)+1
#define FIDX(j) ((j) + ((j) >> 3))

__global__ void __launch_bounds__(512) abuild(const float* __restrict__ img,
                                              const float* __restrict__ cw,
                                              const float* __restrict__ cb) {
    __shared__ float PS[4][SPAN];
    __shared__ float FS[2][FSSZ];
    __shared__ float ELS[2][260], ERS[2][260];

    const int half = blockIdx.x;
    const int hp   = blockIdx.y;         // h pair: rows 2hp, 2hp+1
    const int b    = blockIdx.z;
    const int t    = threadIdx.x;

    const int O = half * 2048;           // strip: g = O - 16 + 4*pi4

    float w[3][3];
#pragma unroll
    for (int i = 0; i < 3; i++)
#pragma unroll
        for (int j = 0; j < 3; j++) w[i][j] = cw[i * 3 + j];
    const float bias = cb[0];

    // interior float4 range [lo4, hi4] (outside: all-1.0 pad or zero row)
    const int lo4 = (half == 0) ? 4 : 0;
    const int hi4 = (half == 0) ? 521 : 515;

    // ---- phase 1: 4 rows x 522 float4 tasks ----
    for (int idx = t; idx < 4 * 522; idx += 512) {
        const int r   = idx / 522;
        const int pi4 = idx - r * 522;
        const int inrow = 2 * hp + r - 1;
        float4 v;
        if ((unsigned)inrow >= 32u) {
            v = make_float4(0.f, 0.f, 0.f, 0.f);
        } else if (pi4 >= lo4 && pi4 <= hi4) {
            const float* rp = img + ((size_t)b * IMG_H + inrow) * IMG_W;
            v = *reinterpret_cast<const float4*>(rp + (O - 16 + pi4 * 4));
        } else {
            v = make_float4(1.f, 1.f, 1.f, 1.f);
        }
        *reinterpret_cast<float4*>(&PS[r][pi4 * 4]) = v;
    }
    __syncthreads();

    // ---- phase 2: F rows + edge partials; 4 outputs per task ----
    for (int idx = t; idx < 2 * NGRP; idx += 512) {
        const int hrow = idx / NGRP;
        const int grp  = idx - hrow * NGRP;
        const int j    = grp * 4;

        float s3[3], s8[3];
        float4 q1[3];
#pragma unroll
        for (int r = 0; r < 3; r++) {
            const float* pr = PS[hrow + r];
            s3[r] = pr[j + 3];
            q1[r] = *reinterpret_cast<const float4*>(pr + j + 4);
            s8[r] = pr[j + 8];
        }
        float f[4], t0_0 = 0.f, t2_3 = 0.f;
#pragma unroll
        for (int jj = 0; jj < 4; jj++) f[jj] = bias;
#pragma unroll
        for (int r = 0; r < 3; r++) {
            const float a0 = s3[r], a1 = q1[r].x, a2 = q1[r].y,
                        a3 = q1[r].z, a4 = q1[r].w, a5 = s8[r];
            f[0] += w[r][0] * a0 + w[r][1] * a1 + w[r][2] * a2;
            f[1] += w[r][0] * a1 + w[r][1] * a2 + w[r][2] * a3;
            f[2] += w[r][0] * a2 + w[r][1] * a3 + w[r][2] * a4;
            f[3] += w[r][0] * a3 + w[r][1] * a4 + w[r][2] * a5;
            t0_0 += w[r][0] * a0;     // left partial of F[j]
            t2_3 += w[r][2] * a5;     // right partial of F[j+3]
        }
        const int fb = FIDX(j);       // contiguous 4 (j mod 8 in {0,4})
#pragma unroll
        for (int jj = 0; jj < 4; jj++) FS[hrow][fb + jj] = f[jj];
        if ((j & 7) == 0) ELS[hrow][j >> 3] = t0_0;
        else              ERS[hrow][j >> 3] = t2_3;   // (j&7)==4
    }
    __syncthreads();

    // ---- phase 3: one (slice, h) per thread ----
    const int sl   = t & 255;
    const int hrow = t >> 8;
    const int s  = half * 256 + sl;
    const size_t gm = (size_t)b * NSLICE + s;
    const size_t mtile = gm >> 7;
    const int row = (int)(gm & 127);
    char* base = (char*)g_A + (mtile * 16 + hp) * 16384 + (size_t)row * 128;

    const float* FSr = FS[hrow];
    const int fbase = 9 * sl;
#pragma unroll
    for (int c8 = 0; c8 < 4; c8++) {
        float v[8];
#pragma unroll
        for (int cc = 0; cc < 8; cc++) {
            const int c = c8 * 8 + cc;
            v[cc] = FSr[fbase + c + (c >> 3)];
        }
        if (c8 == 0) v[0] -= ELS[hrow][sl];
        if (c8 == 3) v[7] -= ERS[hrow][sl + 3];
        uint4 u;
        __half2* hpx = reinterpret_cast<__half2*>(&u);
#pragma unroll
        for (int i = 0; i < 4; i++)
            hpx[i] = __floats2half2_rn(fmaxf(v[2 * i], 0.0f),
                                       fmaxf(v[2 * i + 1], 0.0f));
        const int ch = hrow * 4 + c8;
        *reinterpret_cast<uint4*>(base + ((ch ^ (row & 7)) << 4)) = u;
    }
}

// ---------------------------------------------------------------------------
// Kernel 2 (verbatim): g_W tiled/pre-swizzled fp16 of lin_w^T.
// ---------------------------------------------------------------------------
__global__ void __launch_bounds__(256) prepw(const float* __restrict__ lw) {
    __shared__ float tl[32][33];
    const int tx = threadIdx.x & 31;
    const int ty = threadIdx.x >> 5;      // 0..7
    const int n0 = blockIdx.x * 32;
    const int k0 = blockIdx.y * 32;
#pragma unroll
    for (int i = 0; i < 4; i++)
        tl[ty + 8 * i][tx] = lw[(size_t)(k0 + ty + 8 * i) * NTOT + n0 + tx];
    __syncthreads();
    const int k = k0 + tx;
    const int kc = k >> 6, col = k & 63;
    const int ch = col >> 3, off = (col & 7) * 2;
#pragma unroll
    for (int i = 0; i < 4; i++) {
        const int n = n0 + ty + 8 * i;
        const int bxW = n >> 8, rowW = n & 255;
        char* p = (char*)g_W + ((size_t)(bxW * 16 + kc) * 256 + rowW) * 128 +
                  ((ch ^ (rowW & 7)) << 4) + off;
        *reinterpret_cast<__half*>(p) = __float2half_rn(tl[tx][ty + 8 * i]);
    }
}

// ---------------------------------------------------------------------------
// Kernel 3: PERSISTENT fp16 GEMM. 148 CTAs; CTA bid processes tiles
// tid = bid, bid+148, ... (tile -> by = tid>>1, bx = tid&1; bx constant/CTA).
// The 4-stage bulk-copy ring runs continuously across tiles via a global
// chunk counter g (16 chunks per tile): stage g&3, parity (g>>2)&1. The
// producer prefetches chunk g+4 (possibly next tile) so the next tile's
// operands stream in underneath the current tile's epilogue.
// CTA tile 128x256, 512 threads, warps 2x8, warp tile 64x32.
// ---------------------------------------------------------------------------
#define A_STAGE   16384
#define B_STAGE   32768
#define STAGE_SZ  (A_STAGE + B_STAGE)
#define NSTAGE    4
#define GEMM_SMEM (NSTAGE * STAGE_SZ)     // 192 KB dynamic
#define NTILES    512                     // 256 by x 2 bx
#define GRIDP     148

__global__ void __launch_bounds__(512) gemm(const float* __restrict__ bias,
                                            float* __restrict__ out) {
    extern __shared__ __align__(1024) char dsm[];
    __shared__ __align__(16) uint64_t mbar[NSTAGE];

    const int t    = threadIdx.x;
    const int lane = t & 31;
    const int warp = t >> 5;
    const int wm   = warp >> 3;     // 0..1
    const int wn   = warp & 7;      // 0..7
    const int bid  = blockIdx.x;

    const int ntiles = (NTILES - bid + GRIDP - 1) / GRIDP;   // 3 or 4
    const int nch    = ntiles * 16;

    const uint32_t smem_base = smem_u32(dsm);
    uint32_t mb[NSTAGE];
#pragma unroll
    for (int i = 0; i < NSTAGE; i++) mb[i] = smem_u32(&mbar[i]);

    if (t == 0) {
#pragma unroll
        for (int i = 0; i < NSTAGE; i++) MBARRIER_INIT(mb[i], 1);
        asm volatile("fence.proxy.async.shared::cta;" ::: "memory");
    }
    __syncthreads();

    // issue chunk with global index g (tile tid = bid + 148*(g>>4))
    auto issue = [&](int g) {
        const int s   = g & (NSTAGE - 1);
        const int tid = bid + GRIDP * (g >> 4);
        const int kc  = g & 15;
        const int by  = tid >> 1;
        const int bx  = tid & 1;
        const uint32_t sa = smem_base + s * STAGE_SZ;
        MBARRIER_EXPECT_TX(mb[s], STAGE_SZ);
        bulk_g2s(sa,
                 (const char*)g_A + ((size_t)by * 16 + kc) * A_STAGE,
                 A_STAGE, mb[s]);
        bulk_g2s(sa + A_STAGE,
                 (const char*)g_W + ((size_t)bx * 16 + kc) * B_STAGE,
                 B_STAGE, mb[s]);
    };

    if (t == 0) { issue(0); issue(1); issue(2); issue(3); }

    float c[4][2][2][4];
#pragma unroll
    for (int i = 0; i < 4; i++)
#pragma unroll
        for (int j = 0; j < 2; j++)
#pragma unroll
            for (int k = 0; k < 2; k++)
#pragma unroll
                for (int l = 0; l < 4; l++) c[i][j][k][l] = 0.0f;

    // ldmatrix per-lane address components (within a stage)
    const int rm     = lane & 7;
    const int a_roff = (wm * 64 + (lane & 15)) * 128;                      // + mt*2048
    const int a_m    = lane >> 4;
    const int b_roff = (wn * 32 + ((lane >> 4) << 3) + (lane & 7)) * 128;  // + p*2048
    const int b_m    = (lane >> 3) & 1;

    for (int g = 0; g < nch; g++) {
        const int st  = g & (NSTAGE - 1);
        const int par = (g >> 2) & 1;
        MBARRIER_WAIT_PARITY(mb[st], par);

        const uint32_t sa = smem_base + st * STAGE_SZ;
        const uint32_t sb = sa + A_STAGE;

#pragma unroll
        for (int ks = 0; ks < 4; ks++) {                      // k16 steps
            uint32_t a[4][4], bf[2][4];
#pragma unroll
            for (int mt = 0; mt < 4; mt++)
                ldsm_x4(a[mt], sa + a_roff + mt * 2048 +
                               (((2 * ks + a_m) ^ rm) << 4));
#pragma unroll
            for (int p = 0; p < 2; p++)
                ldsm_x4(bf[p], sb + b_roff + p * 2048 +
                               (((2 * ks + b_m) ^ rm) << 4));
#pragma unroll
            for (int mt = 0; mt < 4; mt++)
#pragma unroll
                for (int p = 0; p < 2; p++) {
                    mma_f16(c[mt][p][0], a[mt], bf[p][0], bf[p][1]);
                    mma_f16(c[mt][p][1], a[mt], bf[p][2], bf[p][3]);
                }
        }

        __syncthreads();                    // stage st drained by all warps
        if (t == 0 && g + NSTAGE < nch) issue(g + NSTAGE);

        if ((g & 15) == 15) {
            // epilogue for finished tile (registers + gmem only; overlaps
            // the in-flight bulk copies of the next tile)
            const int tid = bid + GRIDP * (g >> 4);
            const int by  = tid >> 1;
            const int bx  = tid & 1;
#pragma unroll
            for (int p = 0; p < 2; p++)
#pragma unroll
                for (int ns = 0; ns < 2; ns++) {
                    const int col = bx * 256 + wn * 32 + p * 16 + ns * 8 +
                                    2 * (lane & 3);
                    const float b0 = bias[col], b1 = bias[col + 1];
#pragma unroll
                    for (int mt = 0; mt < 4; mt++) {
                        const int r0 = by * 128 + wm * 64 + mt * 16 + (lane >> 2);
                        float2 v0 = make_float2(c[mt][p][ns][0] + b0,
                                                c[mt][p][ns][1] + b1);
                        float2 v1 = make_float2(c[mt][p][ns][2] + b0,
                                                c[mt][p][ns][3] + b1);
                        *reinterpret_cast<float2*>(&out[(size_t)r0 * NTOT + col])       = v0;
                        *reinterpret_cast<float2*>(&out[(size_t)(r0 + 8) * NTOT + col]) = v1;
                    }
                }
            // reset accumulators for the next tile
#pragma unroll
            for (int i = 0; i < 4; i++)
#pragma unroll
                for (int j = 0; j < 2; j++)
#pragma unroll
                    for (int k = 0; k < 2; k++)
#pragma unroll
                        for (int l = 0; l < 4; l++) c[i][j][k][l] = 0.0f;
        }
    }
}

// ---------------------------------------------------------------------------
extern "C" void kernel_launch(void* const* d_in, const int* in_sizes, int n_in,
                              void* d_out, int out_size) {
    const float* images = (const float*)d_in[0];
    const float* conv_w = (const float*)d_in[1];
    const float* conv_b = (const float*)d_in[2];
    const float* lin_w  = (const float*)d_in[3];
    const float* lin_b  = (const float*)d_in[4];
    float* out = (float*)d_out;

    cudaFuncSetAttribute(gemm, cudaFuncAttributeMaxDynamicSharedMemorySize,
                         GEMM_SMEM);

    abuild<<<dim3(2, 16, IMG_B), 512>>>(images, conv_w, conv_b);
    prepw<<<dim3(NTOT / 32, KTOT / 32), 256>>>(lin_w);
    gemm<<<GRIDP, 512, GEMM_SMEM>>>(lin_b, out);
}

// round 15
// speedup vs baseline: 1.0456x; 1.0456x over previous
#include <cuda_runtime.h>
#include <cuda_fp16.h>
#include <cstdint>
#include <cstddef>

#define IMG_B   64
#define IMG_H   32
#define IMG_W   4096
#define NSLICE  512
#define MTOT    32768
#define KTOT    1024
#define NTOT    512

// Tiled + pre-swizzled operand storage.
//   g_A: [m_tile 0..255][kc 0..15][row 0..127][16B chunk, ch^(row&7)]  64 MB
//   g_W: [bx 0..1][kc 0..15][row 0..255][16B chunk, ch^(row&7)]        1 MB
__device__ __align__(128) __half g_A[(size_t)MTOT * KTOT];
__device__ __align__(128) __half g_W[(size_t)NTOT * KTOT];

// ---------------------------------------------------------------------------
// helpers
// ---------------------------------------------------------------------------
__device__ __forceinline__ uint32_t smem_u32(const void* p) {
    uint32_t a;
    asm("{ .reg .u64 t; cvta.to.shared.u64 t, %1; cvt.u32.u64 %0, t; }" : "=r"(a) : "l"(p));
    return a;
}

__device__ __forceinline__ void ldsm_x4(uint32_t r[4], uint32_t addr) {
    asm volatile("ldmatrix.sync.aligned.m8n8.x4.shared.b16 {%0,%1,%2,%3}, [%4];"
                 : "=r"(r[0]), "=r"(r[1]), "=r"(r[2]), "=r"(r[3]) : "r"(addr));
}

__device__ __forceinline__ void mma_f16(float c[4], const uint32_t a[4],
                                        uint32_t b0, uint32_t b1) {
    asm volatile(
        "mma.sync.aligned.m16n8k16.row.col.f32.f16.f16.f32 "
        "{%0,%1,%2,%3}, {%4,%5,%6,%7}, {%8,%9}, {%0,%1,%2,%3};"
        : "+f"(c[0]), "+f"(c[1]), "+f"(c[2]), "+f"(c[3])
        : "r"(a[0]), "r"(a[1]), "r"(a[2]), "r"(a[3]), "r"(b0), "r"(b1));
}

__device__ __forceinline__ void bulk_g2s(uint32_t sdst, const void* gsrc,
                                         uint32_t bytes, uint32_t mbar) {
    asm volatile(
        "cp.async.bulk.shared::cluster.global.mbarrier::complete_tx::bytes "
        "[%0], [%1], %2, [%3];"
        :: "r"(sdst), "l"(gsrc), "r"(bytes), "r"(mbar) : "memory");
}

#define MBARRIER_INIT(a, c) \
    asm volatile("mbarrier.init.shared.b64 [%0], %1;" :: "r"((uint32_t)(a)), "r"((uint32_t)(c)) : "memory")
#define MBARRIER_EXPECT_TX(a, b) \
    asm volatile("mbarrier.arrive.expect_tx.shared.b64 _, [%0], %1;" :: "r"((uint32_t)(a)), "r"((uint32_t)(b)) : "memory")

#define MBARRIER_WAIT_PARITY(mbar_addr, parity) do { \
    uint32_t _mbar = (uint32_t)(mbar_addr); \
    uint32_t _par  = (uint32_t)(parity); \
    uint32_t _done_; \
    asm volatile("{\n\t.reg .pred p;\n\t" \
        "mbarrier.try_wait.parity.acquire.cta.shared::cta.b64 p, [%1], %2;\n\t" \
        "selp.b32 %0, 1, 0, p;\n\t}" \
        : "=r"(_done_) : "r"(_mbar), "r"(_par) : "memory"); \
    if (!_done_) { \
        asm volatile("{\n\t.reg .pred P1;\n\t" \
            "WAIT_LOOP_%=:\n\t" \
            "mbarrier.try_wait.parity.acquire.cta.shared::cta.b64 P1, [%0], %1, 0x989680;\n\t" \
            "@P1 bra.uni WAIT_DONE_%=;\n\t" \
            "bra.uni WAIT_LOOP_%=;\n\t" \
            "WAIT_DONE_%=:\n\t}" \
            :: "r"(_mbar), "r"(_par) : "memory"); \
    } \
} while (0)

// ---------------------------------------------------------------------------
// Kernel 1 (abuild v4): like v3 but FS padding is +4 per 8 (stride 12), so
// slice-group reads in phase 3 are 16B-aligned contiguous -> 8x LDS.128
// (bank-walk 12*sl mod 32 covers all banks once per 8-lane phase), and
// phase-2 group writes are STS.128. Arithmetic identical to v3.
// Grid (2 halves, 16 h-pairs, 64 b), 512 threads.
// ---------------------------------------------------------------------------
#define SPAN    2088            // padded strip length (522 float4)
#define NGRP    519             // groups of 4 F outputs per h row
#define FIDX12(j) ((j) + (((j) >> 3) << 2))   // stride-12 per 8
#define FSSZ    3120            // >= FIDX12(2075)+1 = 3112

__global__ void __launch_bounds__(512) abuild(const float* __restrict__ img,
                                              const float* __restrict__ cw,
                                              const float* __restrict__ cb) {
    __shared__ float PS[4][SPAN];
    __shared__ __align__(16) float FS[2][FSSZ];
    __shared__ float ELS[2][260], ERS[2][260];

    const int half = blockIdx.x;
    const int hp   = blockIdx.y;         // h pair: rows 2hp, 2hp+1
    const int b    = blockIdx.z;
    const int t    = threadIdx.x;

    const int O = half * 2048;           // strip: g = O - 16 + 4*pi4

    float w[3][3];
#pragma unroll
    for (int i = 0; i < 3; i++)
#pragma unroll
        for (int j = 0; j < 3; j++) w[i][j] = cw[i * 3 + j];
    const float bias = cb[0];

    // interior float4 range [lo4, hi4] (outside: all-1.0 pad or zero row)
    const int lo4 = (half == 0) ? 4 : 0;
    const int hi4 = (half == 0) ? 521 : 515;

    // ---- phase 1: 4 rows x 522 float4 tasks ----
    for (int idx = t; idx < 4 * 522; idx += 512) {
        const int r   = idx / 522;
        const int pi4 = idx - r * 522;
        const int inrow = 2 * hp + r - 1;
        float4 v;
        if ((unsigned)inrow >= 32u) {
            v = make_float4(0.f, 0.f, 0.f, 0.f);
        } else if (pi4 >= lo4 && pi4 <= hi4) {
            const float* rp = img + ((size_t)b * IMG_H + inrow) * IMG_W;
            v = *reinterpret_cast<const float4*>(rp + (O - 16 + pi4 * 4));
        } else {
            v = make_float4(1.f, 1.f, 1.f, 1.f);
        }
        *reinterpret_cast<float4*>(&PS[r][pi4 * 4]) = v;
    }
    __syncthreads();

    // ---- phase 2: F rows + edge partials; 4 outputs per task ----
    for (int idx = t; idx < 2 * NGRP; idx += 512) {
        const int hrow = idx / NGRP;
        const int grp  = idx - hrow * NGRP;
        const int j    = grp * 4;

        float s3[3], s8[3];
        float4 q1[3];
#pragma unroll
        for (int r = 0; r < 3; r++) {
            const float* pr = PS[hrow + r];
            s3[r] = pr[j + 3];
            q1[r] = *reinterpret_cast<const float4*>(pr + j + 4);
            s8[r] = pr[j + 8];
        }
        float4 f;
        float* fp = &f.x;
        float t0_0 = 0.f, t2_3 = 0.f;
#pragma unroll
        for (int jj = 0; jj < 4; jj++) fp[jj] = bias;
#pragma unroll
        for (int r = 0; r < 3; r++) {
            const float a0 = s3[r], a1 = q1[r].x, a2 = q1[r].y,
                        a3 = q1[r].z, a4 = q1[r].w, a5 = s8[r];
            fp[0] += w[r][0] * a0 + w[r][1] * a1 + w[r][2] * a2;
            fp[1] += w[r][0] * a1 + w[r][1] * a2 + w[r][2] * a3;
            fp[2] += w[r][0] * a2 + w[r][1] * a3 + w[r][2] * a4;
            fp[3] += w[r][0] * a3 + w[r][1] * a4 + w[r][2] * a5;
            t0_0 += w[r][0] * a0;     // left partial of F[j]
            t2_3 += w[r][2] * a5;     // right partial of F[j+3]
        }
        // j mod 8 in {0,4} -> FIDX12(j) mod 4 == 0 -> aligned float4 store
        *reinterpret_cast<float4*>(&FS[hrow][FIDX12(j)]) = f;
        if ((j & 7) == 0) ELS[hrow][j >> 3] = t0_0;
        else              ERS[hrow][j >> 3] = t2_3;   // (j&7)==4
    }
    __syncthreads();

    // ---- phase 3: one (slice, h) per thread; 2x LDS.128 per c8 group ----
    const int sl   = t & 255;
    const int hrow = t >> 8;
    const int s  = half * 256 + sl;
    const size_t gm = (size_t)b * NSLICE + s;
    const size_t mtile = gm >> 7;
    const int row = (int)(gm & 127);
    char* base = (char*)g_A + (mtile * 16 + hp) * 16384 + (size_t)row * 128;

    const float* FSr = FS[hrow];
#pragma unroll
    for (int c8 = 0; c8 < 4; c8++) {
        // group c8 of slice sl = 8 contiguous floats at word 12*(sl+c8)
        const float4 va = *reinterpret_cast<const float4*>(&FSr[12 * (sl + c8)]);
        const float4 vb = *reinterpret_cast<const float4*>(&FSr[12 * (sl + c8) + 4]);
        float v[8] = { va.x, va.y, va.z, va.w, vb.x, vb.y, vb.z, vb.w };
        if (c8 == 0) v[0] -= ELS[hrow][sl];
        if (c8 == 3) v[7] -= ERS[hrow][sl + 3];
        uint4 u;
        __half2* hpx = reinterpret_cast<__half2*>(&u);
#pragma unroll
        for (int i = 0; i < 4; i++)
            hpx[i] = __floats2half2_rn(fmaxf(v[2 * i], 0.0f),
                                       fmaxf(v[2 * i + 1], 0.0f));
        const int ch = hrow * 4 + c8;
        *reinterpret_cast<uint4*>(base + ((ch ^ (row & 7)) << 4)) = u;
    }
}

// ---------------------------------------------------------------------------
// Kernel 2 (verbatim): g_W tiled/pre-swizzled fp16 of lin_w^T.
// ---------------------------------------------------------------------------
__global__ void __launch_bounds__(256) prepw(const float* __restrict__ lw) {
    __shared__ float tl[32][33];
    const int tx = threadIdx.x & 31;
    const int ty = threadIdx.x >> 5;      // 0..7
    const int n0 = blockIdx.x * 32;
    const int k0 = blockIdx.y * 32;
#pragma unroll
    for (int i = 0; i < 4; i++)
        tl[ty + 8 * i][tx] = lw[(size_t)(k0 + ty + 8 * i) * NTOT + n0 + tx];
    __syncthreads();
    const int k = k0 + tx;
    const int kc = k >> 6, col = k & 63;
    const int ch = col >> 3, off = (col & 7) * 2;
#pragma unroll
    for (int i = 0; i < 4; i++) {
        const int n = n0 + ty + 8 * i;
        const int bxW = n >> 8, rowW = n & 255;
        char* p = (char*)g_W + ((size_t)(bxW * 16 + kc) * 256 + rowW) * 128 +
                  ((ch ^ (rowW & 7)) << 4) + off;
        *reinterpret_cast<__half*>(p) = __float2half_rn(tl[tx][ty + 8 * i]);
    }
}

// ---------------------------------------------------------------------------
// Kernel 3 (round-11 verbatim, the 140.0us config): fp16 GEMM, mma.sync +
// ldmatrix, cp.async.bulk + mbarrier. CTA tile 128x256, 4-stage ring (192KB),
// 512 threads, warps 2x8, warp tile 64x32. Grid (2, 256).
// ---------------------------------------------------------------------------
#define A_STAGE   16384
#define B_STAGE   32768
#define STAGE_SZ  (A_STAGE + B_STAGE)
#define NSTAGE    4
#define GEMM_SMEM (NSTAGE * STAGE_SZ)     // 192 KB dynamic
#define KCHUNKS   16

__global__ void __launch_bounds__(512) gemm(const float* __restrict__ bias,
                                            float* __restrict__ out) {
    extern __shared__ __align__(1024) char dsm[];
    __shared__ __align__(16) uint64_t mbar[NSTAGE];

    const int t    = threadIdx.x;
    const int lane = t & 31;
    const int warp = t >> 5;
    const int wm   = warp >> 3;     // 0..1
    const int wn   = warp & 7;      // 0..7
    const int bx   = blockIdx.x;    // N block (0..1)
    const int by   = blockIdx.y;    // M block (0..255)

    const uint32_t smem_base = smem_u32(dsm);
    uint32_t mb[NSTAGE];
#pragma unroll
    for (int i = 0; i < NSTAGE; i++) mb[i] = smem_u32(&mbar[i]);

    const char* Abase = (const char*)g_A + (size_t)by * 16 * 16384;
    const char* Bbase = (const char*)g_W + (size_t)bx * 16 * 32768;

    if (t == 0) {
#pragma unroll
        for (int i = 0; i < NSTAGE; i++) MBARRIER_INIT(mb[i], 1);
        asm volatile("fence.proxy.async.shared::cta;" ::: "memory");
    }
    __syncthreads();

    auto issue = [&](int kc) {
        const int s = kc & (NSTAGE - 1);
        const uint32_t sa = smem_base + s * STAGE_SZ;
        MBARRIER_EXPECT_TX(mb[s], STAGE_SZ);
        bulk_g2s(sa,           Abase + (size_t)kc * A_STAGE, A_STAGE, mb[s]);
        bulk_g2s(sa + A_STAGE, Bbase + (size_t)kc * B_STAGE, B_STAGE, mb[s]);
    };

    if (t == 0) { issue(0); issue(1); issue(2); issue(3); }

    float c[4][2][2][4];
#pragma unroll
    for (int i = 0; i < 4; i++)
#pragma unroll
        for (int j = 0; j < 2; j++)
#pragma unroll
            for (int k = 0; k < 2; k++)
#pragma unroll
                for (int l = 0; l < 4; l++) c[i][j][k][l] = 0.0f;

    // ldmatrix per-lane address components (within a stage)
    const int rm     = lane & 7;
    const int a_roff = (wm * 64 + (lane & 15)) * 128;                      // + mt*2048
    const int a_m    = lane >> 4;
    const int b_roff = (wn * 32 + ((lane >> 4) << 3) + (lane & 7)) * 128;  // + p*2048
    const int b_m    = (lane >> 3) & 1;

    for (int kc = 0; kc < KCHUNKS; kc++) {
        const int st = kc & (NSTAGE - 1);
        MBARRIER_WAIT_PARITY(mb[st], (kc >> 2) & 1);

        const uint32_t sa = smem_base + st * STAGE_SZ;
        const uint32_t sb = sa + A_STAGE;

#pragma unroll
        for (int ks = 0; ks < 4; ks++) {                      // k16 steps
            uint32_t a[4][4], bf[2][4];
#pragma unroll
            for (int mt = 0; mt < 4; mt++)
                ldsm_x4(a[mt], sa + a_roff + mt * 2048 +
                               (((2 * ks + a_m) ^ rm) << 4));
#pragma unroll
            for (int p = 0; p < 2; p++)
                ldsm_x4(bf[p], sb + b_roff + p * 2048 +
                               (((2 * ks + b_m) ^ rm) << 4));
#pragma unroll
            for (int mt = 0; mt < 4; mt++)
#pragma unroll
                for (int p = 0; p < 2; p++) {
                    mma_f16(c[mt][p][0], a[mt], bf[p][0], bf[p][1]);
                    mma_f16(c[mt][p][1], a[mt], bf[p][2], bf[p][3]);
                }
        }

        __syncthreads();                    // all warps done reading stage st
        if (t == 0 && kc + NSTAGE < KCHUNKS) issue(kc + NSTAGE);
    }

    // epilogue: += bias, write fp32
#pragma unroll
    for (int p = 0; p < 2; p++)
#pragma unroll
        for (int ns = 0; ns < 2; ns++) {
            const int col = bx * 256 + wn * 32 + p * 16 + ns * 8 + 2 * (lane & 3);
            const float b0 = bias[col], b1 = bias[col + 1];
#pragma unroll
            for (int mt = 0; mt < 4; mt++) {
                const int r0 = by * 128 + wm * 64 + mt * 16 + (lane >> 2);
                float2 v0 = make_float2(c[mt][p][ns][0] + b0, c[mt][p][ns][1] + b1);
                float2 v1 = make_float2(c[mt][p][ns][2] + b0, c[mt][p][ns][3] + b1);
                *reinterpret_cast<float2*>(&out[(size_t)r0 * NTOT + col])       = v0;
                *reinterpret_cast<float2*>(&out[(size_t)(r0 + 8) * NTOT + col]) = v1;
            }
        }
}

// ---------------------------------------------------------------------------
extern "C" void kernel_launch(void* const* d_in, const int* in_sizes, int n_in,
                              void* d_out, int out_size) {
    const float* images = (const float*)d_in[0];
    const float* conv_w = (const float*)d_in[1];
    const float* conv_b = (const float*)d_in[2];
    const float* lin_w  = (const float*)d_in[3];
    const float* lin_b  = (const float*)d_in[4];
    float* out = (float*)d_out;

    cudaFuncSetAttribute(gemm, cudaFuncAttributeMaxDynamicSharedMemorySize,
                         GEMM_SMEM);

    abuild<<<dim3(2, 16, IMG_B), 512>>>(images, conv_w, conv_b);
    prepw<<<dim3(NTOT / 32, KTOT / 32), 256>>>(lin_w);
    gemm<<<dim3(NTOT / 256, MTOT / 128), 512, GEMM_SMEM>>>(lin_b, out);
}

// round 16
// speedup vs baseline: 1.0881x; 1.0406x over previous
#include <cuda_runtime.h>
#include <cuda_fp16.h>
#include <cstdint>
#include <cstddef>

#define IMG_B   64
#define IMG_H   32
#define IMG_W   4096
#define NSLICE  512
#define MTOT    32768
#define KTOT    1024
#define NTOT    512

// Tiled + pre-swizzled operand storage.
//   g_A: [m_tile 0..255][kc 0..15][row 0..127][16B chunk, ch^(row&7)]  64 MB
//   g_W: [bx 0..1][kc 0..15][row 0..255][16B chunk, ch^(row&7)]        1 MB
__device__ __align__(128) __half g_A[(size_t)MTOT * KTOT];
__device__ __align__(128) __half g_W[(size_t)NTOT * KTOT];

// ---------------------------------------------------------------------------
// helpers
// ---------------------------------------------------------------------------
__device__ __forceinline__ uint32_t smem_u32(const void* p) {
    uint32_t a;
    asm("{ .reg .u64 t; cvta.to.shared.u64 t, %1; cvt.u32.u64 %0, t; }" : "=r"(a) : "l"(p));
    return a;
}

__device__ __forceinline__ void ldsm_x4(uint32_t r[4], uint32_t addr) {
    asm volatile("ldmatrix.sync.aligned.m8n8.x4.shared.b16 {%0,%1,%2,%3}, [%4];"
                 : "=r"(r[0]), "=r"(r[1]), "=r"(r[2]), "=r"(r[3]) : "r"(addr));
}

__device__ __forceinline__ void mma_f16(float c[4], const uint32_t a[4],
                                        uint32_t b0, uint32_t b1) {
    asm volatile(
        "mma.sync.aligned.m16n8k16.row.col.f32.f16.f16.f32 "
        "{%0,%1,%2,%3}, {%4,%5,%6,%7}, {%8,%9}, {%0,%1,%2,%3};"
        : "+f"(c[0]), "+f"(c[1]), "+f"(c[2]), "+f"(c[3])
        : "r"(a[0]), "r"(a[1]), "r"(a[2]), "r"(a[3]), "r"(b0), "r"(b1));
}

__device__ __forceinline__ void bulk_g2s(uint32_t sdst, const void* gsrc,
                                         uint32_t bytes, uint32_t mbar) {
    asm volatile(
        "cp.async.bulk.shared::cluster.global.mbarrier::complete_tx::bytes "
        "[%0], [%1], %2, [%3];"
        :: "r"(sdst), "l"(gsrc), "r"(bytes), "r"(mbar) : "memory");
}

#define MBARRIER_INIT(a, c) \
    asm volatile("mbarrier.init.shared.b64 [%0], %1;" :: "r"((uint32_t)(a)), "r"((uint32_t)(c)) : "memory")
#define MBARRIER_EXPECT_TX(a, b) \
    asm volatile("mbarrier.arrive.expect_tx.shared.b64 _, [%0], %1;" :: "r"((uint32_t)(a)), "r"((uint32_t)(b)) : "memory")

#define MBARRIER_WAIT_PARITY(mbar_addr, parity) do { \
    uint32_t _mbar = (uint32_t)(mbar_addr); \
    uint32_t _par  = (uint32_t)(parity); \
    uint32_t _done_; \
    asm volatile("{\n\t.reg .pred p;\n\t" \
        "mbarrier.try_wait.parity.acquire.cta.shared::cta.b64 p, [%1], %2;\n\t" \
        "selp.b32 %0, 1, 0, p;\n\t}" \
        : "=r"(_done_) : "r"(_mbar), "r"(_par) : "memory"); \
    if (!_done_) { \
        asm volatile("{\n\t.reg .pred P1;\n\t" \
            "WAIT_LOOP_%=:\n\t" \
            "mbarrier.try_wait.parity.acquire.cta.shared::cta.b64 P1, [%0], %1, 0x989680;\n\t" \
            "@P1 bra.uni WAIT_DONE_%=;\n\t" \
            "bra.uni WAIT_LOOP_%=;\n\t" \
            "WAIT_DONE_%=:\n\t}" \
            :: "r"(_mbar), "r"(_par) : "memory"); \
    } \
} while (0)

// ---------------------------------------------------------------------------
// Kernel 1 (abuild v5): phase-1 staging DELETED. Phase 2 computes F rows +
// edge partials reading the padded image directly from gmem (predicated,
// clamped, alignment-safe: pad boundaries are mod-4 so the float4 load never
// straddles; values are bit-identical to the old PS contents, FMA order
// unchanged). Phase 3 (gather + fixup + fp16 swizzled store) identical to v4.
// smem 63KB -> 29KB: 4 blocks/SM (warp-limited), occ -> ~100%.
// Grid (2 halves, 16 h-pairs, 64 b), 512 threads.
// ---------------------------------------------------------------------------
#define NGRP    519             // groups of 4 F outputs per h row
#define FIDX12(j) ((j) + (((j) >> 3) << 2))   // stride-12 per 8
#define FSSZ    3120            // >= FIDX12(2072)+4 = 3112

__global__ void __launch_bounds__(512) abuild(const float* __restrict__ img,
                                              const float* __restrict__ cw,
                                              const float* __restrict__ cb) {
    __shared__ __align__(16) float FS[2][FSSZ];
    __shared__ float ELS[2][260], ERS[2][260];

    const int half = blockIdx.x;
    const int hp   = blockIdx.y;         // h pair: rows 2hp, 2hp+1
    const int b    = blockIdx.z;
    const int t    = threadIdx.x;

    const int O = half * 2048;

    float w[3][3];
#pragma unroll
    for (int i = 0; i < 3; i++)
#pragma unroll
        for (int j = 0; j < 3; j++) w[i][j] = cw[i * 3 + j];
    const float bias = cb[0];

    // ---- phase 2: F rows + edge partials straight from gmem ----
    for (int idx = t; idx < 2 * NGRP; idx += 512) {
        const int hrow = idx / NGRP;
        const int grp  = idx - hrow * NGRP;
        const int j    = grp * 4;

        // global image columns for strip positions j+3 / j+4..j+7 / j+8
        const int g3 = O + j - 13;
        const int g4 = O + j - 12;           // aligned (O%2048==0, j%4==0)
        const int g8 = O + j - 8;
        const bool in3 = (unsigned)g3 < 4096u;
        const bool in4 = (unsigned)g4 <= 4092u;   // fully-interior float4
        const bool in8 = (unsigned)g8 < 4096u;
        const int cg3 = in3 ? g3 : 0;
        const int cg4 = in4 ? g4 : 0;
        const int cg8 = in8 ? g8 : 0;

        float s3[3], s8[3];
        float4 q1[3];
#pragma unroll
        for (int r = 0; r < 3; r++) {
            const int inrow = 2 * hp + hrow + r - 1;
            const bool rowok = (unsigned)inrow < 32u;
            const float* rp = img + ((size_t)b * IMG_H + (rowok ? inrow : 0)) * IMG_W;
            const float pad = rowok ? 1.0f : 0.0f;
            s3[r] = (rowok && in3) ? __ldg(rp + cg3) : pad;
            s8[r] = (rowok && in8) ? __ldg(rp + cg8) : pad;
            if (rowok && in4)
                q1[r] = *reinterpret_cast<const float4*>(rp + cg4);
            else
                q1[r] = make_float4(pad, pad, pad, pad);
        }

        float4 f;
        float* fp = &f.x;
        float t0_0 = 0.f, t2_3 = 0.f;
#pragma unroll
        for (int jj = 0; jj < 4; jj++) fp[jj] = bias;
#pragma unroll
        for (int r = 0; r < 3; r++) {
            const float a0 = s3[r], a1 = q1[r].x, a2 = q1[r].y,
                        a3 = q1[r].z, a4 = q1[r].w, a5 = s8[r];
            fp[0] += w[r][0] * a0 + w[r][1] * a1 + w[r][2] * a2;
            fp[1] += w[r][0] * a1 + w[r][1] * a2 + w[r][2] * a3;
            fp[2] += w[r][0] * a2 + w[r][1] * a3 + w[r][2] * a4;
            fp[3] += w[r][0] * a3 + w[r][1] * a4 + w[r][2] * a5;
            t0_0 += w[r][0] * a0;     // left partial of F[j]
            t2_3 += w[r][2] * a5;     // right partial of F[j+3]
        }
        // j mod 8 in {0,4} -> FIDX12(j) mod 4 == 0 -> aligned float4 store
        *reinterpret_cast<float4*>(&FS[hrow][FIDX12(j)]) = f;
        if ((j & 7) == 0) ELS[hrow][j >> 3] = t0_0;
        else              ERS[hrow][j >> 3] = t2_3;   // (j&7)==4
    }
    __syncthreads();

    // ---- phase 3: one (slice, h) per thread; 2x LDS.128 per c8 group ----
    const int sl   = t & 255;
    const int hrow = t >> 8;
    const int s  = half * 256 + sl;
    const size_t gm = (size_t)b * NSLICE + s;
    const size_t mtile = gm >> 7;
    const int row = (int)(gm & 127);
    char* base = (char*)g_A + (mtile * 16 + hp) * 16384 + (size_t)row * 128;

    const float* FSr = FS[hrow];
#pragma unroll
    for (int c8 = 0; c8 < 4; c8++) {
        const float4 va = *reinterpret_cast<const float4*>(&FSr[12 * (sl + c8)]);
        const float4 vb = *reinterpret_cast<const float4*>(&FSr[12 * (sl + c8) + 4]);
        float v[8] = { va.x, va.y, va.z, va.w, vb.x, vb.y, vb.z, vb.w };
        if (c8 == 0) v[0] -= ELS[hrow][sl];
        if (c8 == 3) v[7] -= ERS[hrow][sl + 3];
        uint4 u;
        __half2* hpx = reinterpret_cast<__half2*>(&u);
#pragma unroll
        for (int i = 0; i < 4; i++)
            hpx[i] = __floats2half2_rn(fmaxf(v[2 * i], 0.0f),
                                       fmaxf(v[2 * i + 1], 0.0f));
        const int ch = hrow * 4 + c8;
        *reinterpret_cast<uint4*>(base + ((ch ^ (row & 7)) << 4)) = u;
    }
}

// ---------------------------------------------------------------------------
// Kernel 2 (verbatim): g_W tiled/pre-swizzled fp16 of lin_w^T.
// ---------------------------------------------------------------------------
__global__ void __launch_bounds__(256) prepw(const float* __restrict__ lw) {
    __shared__ float tl[32][33];
    const int tx = threadIdx.x & 31;
    const int ty = threadIdx.x >> 5;      // 0..7
    const int n0 = blockIdx.x * 32;
    const int k0 = blockIdx.y * 32;
#pragma unroll
    for (int i = 0; i < 4; i++)
        tl[ty + 8 * i][tx] = lw[(size_t)(k0 + ty + 8 * i) * NTOT + n0 + tx];
    __syncthreads();
    const int k = k0 + tx;
    const int kc = k >> 6, col = k & 63;
    const int ch = col >> 3, off = (col & 7) * 2;
#pragma unroll
    for (int i = 0; i < 4; i++) {
        const int n = n0 + ty + 8 * i;
        const int bxW = n >> 8, rowW = n & 255;
        char* p = (char*)g_W + ((size_t)(bxW * 16 + kc) * 256 + rowW) * 128 +
                  ((ch ^ (rowW & 7)) << 4) + off;
        *reinterpret_cast<__half*>(p) = __float2half_rn(tl[tx][ty + 8 * i]);
    }
}

// ---------------------------------------------------------------------------
// Kernel 3 (verbatim, the 139.5us config): fp16 GEMM, mma.sync + ldmatrix,
// cp.async.bulk + mbarrier. CTA tile 128x256, 4-stage ring (192KB), 512
// threads, warps 2x8, warp tile 64x32. Grid (2, 256).
// ---------------------------------------------------------------------------
#define A_STAGE   16384
#define B_STAGE   32768
#define STAGE_SZ  (A_STAGE + B_STAGE)
#define NSTAGE    4
#define GEMM_SMEM (NSTAGE * STAGE_SZ)     // 192 KB dynamic
#define KCHUNKS   16

__global__ void __launch_bounds__(512) gemm(const float* __restrict__ bias,
                                            float* __restrict__ out) {
    extern __shared__ __align__(1024) char dsm[];
    __shared__ __align__(16) uint64_t mbar[NSTAGE];

    const int t    = threadIdx.x;
    const int lane = t & 31;
    const int warp = t >> 5;
    const int wm   = warp >> 3;     // 0..1
    const int wn   = warp & 7;      // 0..7
    const int bx   = blockIdx.x;    // N block (0..1)
    const int by   = blockIdx.y;    // M block (0..255)

    const uint32_t smem_base = smem_u32(dsm);
    uint32_t mb[NSTAGE];
#pragma unroll
    for (int i = 0; i < NSTAGE; i++) mb[i] = smem_u32(&mbar[i]);

    const char* Abase = (const char*)g_A + (size_t)by * 16 * 16384;
    const char* Bbase = (const char*)g_W + (size_t)bx * 16 * 32768;

    if (t == 0) {
#pragma unroll
        for (int i = 0; i < NSTAGE; i++) MBARRIER_INIT(mb[i], 1);
        asm volatile("fence.proxy.async.shared::cta;" ::: "memory");
    }
    __syncthreads();

    auto issue = [&](int kc) {
        const int s = kc & (NSTAGE - 1);
        const uint32_t sa = smem_base + s * STAGE_SZ;
        MBARRIER_EXPECT_TX(mb[s], STAGE_SZ);
        bulk_g2s(sa,           Abase + (size_t)kc * A_STAGE, A_STAGE, mb[s]);
        bulk_g2s(sa + A_STAGE, Bbase + (size_t)kc * B_STAGE, B_STAGE, mb[s]);
    };

    if (t == 0) { issue(0); issue(1); issue(2); issue(3); }

    float c[4][2][2][4];
#pragma unroll
    for (int i = 0; i < 4; i++)
#pragma unroll
        for (int j = 0; j < 2; j++)
#pragma unroll
            for (int k = 0; k < 2; k++)
#pragma unroll
                for (int l = 0; l < 4; l++) c[i][j][k][l] = 0.0f;

    // ldmatrix per-lane address components (within a stage)
    const int rm     = lane & 7;
    const int a_roff = (wm * 64 + (lane & 15)) * 128;                      // + mt*2048
    const int a_m    = lane >> 4;
    const int b_roff = (wn * 32 + ((lane >> 4) << 3) + (lane & 7)) * 128;  // + p*2048
    const int b_m    = (lane >> 3) & 1;

    for (int kc = 0; kc < KCHUNKS; kc++) {
        const int st = kc & (NSTAGE - 1);
        MBARRIER_WAIT_PARITY(mb[st], (kc >> 2) & 1);

        const uint32_t sa = smem_base + st * STAGE_SZ;
        const uint32_t sb = sa + A_STAGE;

#pragma unroll
        for (int ks = 0; ks < 4; ks++) {                      // k16 steps
            uint32_t a[4][4], bf[2][4];
#pragma unroll
            for (int mt = 0; mt < 4; mt++)
                ldsm_x4(a[mt], sa + a_roff + mt * 2048 +
                               (((2 * ks + a_m) ^ rm) << 4));
#pragma unroll
            for (int p = 0; p < 2; p++)
                ldsm_x4(bf[p], sb + b_roff + p * 2048 +
                               (((2 * ks + b_m) ^ rm) << 4));
#pragma unroll
            for (int mt = 0; mt < 4; mt++)
#pragma unroll
                for (int p = 0; p < 2; p++) {
                    mma_f16(c[mt][p][0], a[mt], bf[p][0], bf[p][1]);
                    mma_f16(c[mt][p][1], a[mt], bf[p][2], bf[p][3]);
                }
        }

        __syncthreads();                    // all warps done reading stage st
        if (t == 0 && kc + NSTAGE < KCHUNKS) issue(kc + NSTAGE);
    }

    // epilogue: += bias, write fp32
#pragma unroll
    for (int p = 0; p < 2; p++)
#pragma unroll
        for (int ns = 0; ns < 2; ns++) {
            const int col = bx * 256 + wn * 32 + p * 16 + ns * 8 + 2 * (lane & 3);
            const float b0 = bias[col], b1 = bias[col + 1];
#pragma unroll
            for (int mt = 0; mt < 4; mt++) {
                const int r0 = by * 128 + wm * 64 + mt * 16 + (lane >> 2);
                float2 v0 = make_float2(c[mt][p][ns][0] + b0, c[mt][p][ns][1] + b1);
                float2 v1 = make_float2(c[mt][p][ns][2] + b0, c[mt][p][ns][3] + b1);
                *reinterpret_cast<float2*>(&out[(size_t)r0 * NTOT + col])       = v0;
                *reinterpret_cast<float2*>(&out[(size_t)(r0 + 8) * NTOT + col]) = v1;
            }
        }
}

// ---------------------------------------------------------------------------
extern "C" void kernel_launch(void* const* d_in, const int* in_sizes, int n_in,
                              void* d_out, int out_size) {
    const float* images = (const float*)d_in[0];
    const float* conv_w = (const float*)d_in[1];
    const float* conv_b = (const float*)d_in[2];
    const float* lin_w  = (const float*)d_in[3];
    const float* lin_b  = (const float*)d_in[4];
    float* out = (float*)d_out;

    cudaFuncSetAttribute(gemm, cudaFuncAttributeMaxDynamicSharedMemorySize,
                         GEMM_SMEM);

    abuild<<<dim3(2, 16, IMG_B), 512>>>(images, conv_w, conv_b);
    prepw<<<dim3(NTOT / 32, KTOT / 32), 256>>>(lin_w);
    gemm<<<dim3(NTOT / 256, MTOT / 128), 512, GEMM_SMEM>>>(lin_b, out);
}

// round 17
// speedup vs baseline: 1.1103x; 1.0205x over previous
#include <cuda_runtime.h>
#include <cuda_fp16.h>
#include <cstdint>
#include <cstddef>

#define IMG_B   64
#define IMG_H   32
#define IMG_W   4096
#define NSLICE  512
#define MTOT    32768
#define KTOT    1024
#define NTOT    512

// Tiled + pre-swizzled operand storage.
//   g_A: [m_tile 0..255][kc 0..15][row 0..127][16B chunk, ch^(row&7)]  64 MB
//   g_W: [bx 0..1][kc 0..15][row 0..255][16B chunk, ch^(row&7)]        1 MB
__device__ __align__(128) __half g_A[(size_t)MTOT * KTOT];
__device__ __align__(128) __half g_W[(size_t)NTOT * KTOT];

// ---------------------------------------------------------------------------
// helpers
// ---------------------------------------------------------------------------
__device__ __forceinline__ uint32_t smem_u32(const void* p) {
    uint32_t a;
    asm("{ .reg .u64 t; cvta.to.shared.u64 t, %1; cvt.u32.u64 %0, t; }" : "=r"(a) : "l"(p));
    return a;
}

__device__ __forceinline__ void ldsm_x4(uint32_t r[4], uint32_t addr) {
    asm volatile("ldmatrix.sync.aligned.m8n8.x4.shared.b16 {%0,%1,%2,%3}, [%4];"
                 : "=r"(r[0]), "=r"(r[1]), "=r"(r[2]), "=r"(r[3]) : "r"(addr));
}

__device__ __forceinline__ void mma_f16(float c[4], const uint32_t a[4],
                                        uint32_t b0, uint32_t b1) {
    asm volatile(
        "mma.sync.aligned.m16n8k16.row.col.f32.f16.f16.f32 "
        "{%0,%1,%2,%3}, {%4,%5,%6,%7}, {%8,%9}, {%0,%1,%2,%3};"
        : "+f"(c[0]), "+f"(c[1]), "+f"(c[2]), "+f"(c[3])
        : "r"(a[0]), "r"(a[1]), "r"(a[2]), "r"(a[3]), "r"(b0), "r"(b1));
}

__device__ __forceinline__ void bulk_g2s(uint32_t sdst, const void* gsrc,
                                         uint32_t bytes, uint32_t mbar) {
    asm volatile(
        "cp.async.bulk.shared::cluster.global.mbarrier::complete_tx::bytes "
        "[%0], [%1], %2, [%3];"
        :: "r"(sdst), "l"(gsrc), "r"(bytes), "r"(mbar) : "memory");
}

#define MBARRIER_INIT(a, c) \
    asm volatile("mbarrier.init.shared.b64 [%0], %1;" :: "r"((uint32_t)(a)), "r"((uint32_t)(c)) : "memory")
#define MBARRIER_EXPECT_TX(a, b) \
    asm volatile("mbarrier.arrive.expect_tx.shared.b64 _, [%0], %1;" :: "r"((uint32_t)(a)), "r"((uint32_t)(b)) : "memory")

#define MBARRIER_WAIT_PARITY(mbar_addr, parity) do { \
    uint32_t _mbar = (uint32_t)(mbar_addr); \
    uint32_t _par  = (uint32_t)(parity); \
    uint32_t _done_; \
    asm volatile("{\n\t.reg .pred p;\n\t" \
        "mbarrier.try_wait.parity.acquire.cta.shared::cta.b64 p, [%1], %2;\n\t" \
        "selp.b32 %0, 1, 0, p;\n\t}" \
        : "=r"(_done_) : "r"(_mbar), "r"(_par) : "memory"); \
    if (!_done_) { \
        asm volatile("{\n\t.reg .pred P1;\n\t" \
            "WAIT_LOOP_%=:\n\t" \
            "mbarrier.try_wait.parity.acquire.cta.shared::cta.b64 P1, [%0], %1, 0x989680;\n\t" \
            "@P1 bra.uni WAIT_DONE_%=;\n\t" \
            "bra.uni WAIT_LOOP_%=;\n\t" \
            "WAIT_DONE_%=:\n\t}" \
            :: "r"(_mbar), "r"(_par) : "memory"); \
    } \
} while (0)

// ---------------------------------------------------------------------------
// Kernel 1 (abuild v5 + occupancy pin): identical arithmetic to the passing
// round-16 version; __launch_bounds__(512, 4) caps regs at 32 so 4 blocks
// co-reside per SM (64 warps) instead of 3 (reg-limited at 40 regs).
// Grid (2 halves, 16 h-pairs, 64 b), 512 threads.
// ---------------------------------------------------------------------------
#define NGRP    519             // groups of 4 F outputs per h row
#define FIDX12(j) ((j) + (((j) >> 3) << 2))   // stride-12 per 8
#define FSSZ    3120            // >= FIDX12(2072)+4 = 3112

__global__ void __launch_bounds__(512, 4) abuild(const float* __restrict__ img,
                                                 const float* __restrict__ cw,
                                                 const float* __restrict__ cb) {
    __shared__ __align__(16) float FS[2][FSSZ];
    __shared__ float ELS[2][260], ERS[2][260];

    const int half = blockIdx.x;
    const int hp   = blockIdx.y;         // h pair: rows 2hp, 2hp+1
    const int b    = blockIdx.z;
    const int t    = threadIdx.x;

    const int O = half * 2048;

    float w[3][3];
#pragma unroll
    for (int i = 0; i < 3; i++)
#pragma unroll
        for (int j = 0; j < 3; j++) w[i][j] = cw[i * 3 + j];
    const float bias = cb[0];

    // ---- phase 2: F rows + edge partials straight from gmem ----
    for (int idx = t; idx < 2 * NGRP; idx += 512) {
        const int hrow = idx / NGRP;
        const int grp  = idx - hrow * NGRP;
        const int j    = grp * 4;

        // global image columns for strip positions j+3 / j+4..j+7 / j+8
        const int g3 = O + j - 13;
        const int g4 = O + j - 12;           // aligned (O%2048==0, j%4==0)
        const int g8 = O + j - 8;
        const bool in3 = (unsigned)g3 < 4096u;
        const bool in4 = (unsigned)g4 <= 4092u;   // fully-interior float4
        const bool in8 = (unsigned)g8 < 4096u;
        const int cg3 = in3 ? g3 : 0;
        const int cg4 = in4 ? g4 : 0;
        const int cg8 = in8 ? g8 : 0;

        float s3[3], s8[3];
        float4 q1[3];
#pragma unroll
        for (int r = 0; r < 3; r++) {
            const int inrow = 2 * hp + hrow + r - 1;
            const bool rowok = (unsigned)inrow < 32u;
            const float* rp = img + ((size_t)b * IMG_H + (rowok ? inrow : 0)) * IMG_W;
            const float pad = rowok ? 1.0f : 0.0f;
            s3[r] = (rowok && in3) ? __ldg(rp + cg3) : pad;
            s8[r] = (rowok && in8) ? __ldg(rp + cg8) : pad;
            if (rowok && in4)
                q1[r] = *reinterpret_cast<const float4*>(rp + cg4);
            else
                q1[r] = make_float4(pad, pad, pad, pad);
        }

        float4 f;
        float* fp = &f.x;
        float t0_0 = 0.f, t2_3 = 0.f;
#pragma unroll
        for (int jj = 0; jj < 4; jj++) fp[jj] = bias;
#pragma unroll
        for (int r = 0; r < 3; r++) {
            const float a0 = s3[r], a1 = q1[r].x, a2 = q1[r].y,
                        a3 = q1[r].z, a4 = q1[r].w, a5 = s8[r];
            fp[0] += w[r][0] * a0 + w[r][1] * a1 + w[r][2] * a2;
            fp[1] += w[r][0] * a1 + w[r][1] * a2 + w[r][2] * a3;
            fp[2] += w[r][0] * a2 + w[r][1] * a3 + w[r][2] * a4;
            fp[3] += w[r][0] * a3 + w[r][1] * a4 + w[r][2] * a5;
            t0_0 += w[r][0] * a0;     // left partial of F[j]
            t2_3 += w[r][2] * a5;     // right partial of F[j+3]
        }
        // j mod 8 in {0,4} -> FIDX12(j) mod 4 == 0 -> aligned float4 store
        *reinterpret_cast<float4*>(&FS[hrow][FIDX12(j)]) = f;
        if ((j & 7) == 0) ELS[hrow][j >> 3] = t0_0;
        else              ERS[hrow][j >> 3] = t2_3;   // (j&7)==4
    }
    __syncthreads();

    // ---- phase 3: one (slice, h) per thread; 2x LDS.128 per c8 group ----
    const int sl   = t & 255;
    const int hrow = t >> 8;
    const int s  = half * 256 + sl;
    const size_t gm = (size_t)b * NSLICE + s;
    const size_t mtile = gm >> 7;
    const int row = (int)(gm & 127);
    char* base = (char*)g_A + (mtile * 16 + hp) * 16384 + (size_t)row * 128;

    const float* FSr = FS[hrow];
#pragma unroll
    for (int c8 = 0; c8 < 4; c8++) {
        const float4 va = *reinterpret_cast<const float4*>(&FSr[12 * (sl + c8)]);
        const float4 vb = *reinterpret_cast<const float4*>(&FSr[12 * (sl + c8) + 4]);
        float v[8] = { va.x, va.y, va.z, va.w, vb.x, vb.y, vb.z, vb.w };
        if (c8 == 0) v[0] -= ELS[hrow][sl];
        if (c8 == 3) v[7] -= ERS[hrow][sl + 3];
        uint4 u;
        __half2* hpx = reinterpret_cast<__half2*>(&u);
#pragma unroll
        for (int i = 0; i < 4; i++)
            hpx[i] = __floats2half2_rn(fmaxf(v[2 * i], 0.0f),
                                       fmaxf(v[2 * i + 1], 0.0f));
        const int ch = hrow * 4 + c8;
        *reinterpret_cast<uint4*>(base + ((ch ^ (row & 7)) << 4)) = u;
    }
}

// ---------------------------------------------------------------------------
// Kernel 2 (verbatim): g_W tiled/pre-swizzled fp16 of lin_w^T.
// ---------------------------------------------------------------------------
__global__ void __launch_bounds__(256) prepw(const float* __restrict__ lw) {
    __shared__ float tl[32][33];
    const int tx = threadIdx.x & 31;
    const int ty = threadIdx.x >> 5;      // 0..7
    const int n0 = blockIdx.x * 32;
    const int k0 = blockIdx.y * 32;
#pragma unroll
    for (int i = 0; i < 4; i++)
        tl[ty + 8 * i][tx] = lw[(size_t)(k0 + ty + 8 * i) * NTOT + n0 + tx];
    __syncthreads();
    const int k = k0 + tx;
    const int kc = k >> 6, col = k & 63;
    const int ch = col >> 3, off = (col & 7) * 2;
#pragma unroll
    for (int i = 0; i < 4; i++) {
        const int n = n0 + ty + 8 * i;
        const int bxW = n >> 8, rowW = n & 255;
        char* p = (char*)g_W + ((size_t)(bxW * 16 + kc) * 256 + rowW) * 128 +
                  ((ch ^ (rowW & 7)) << 4) + off;
        *reinterpret_cast<__half*>(p) = __float2half_rn(tl[tx][ty + 8 * i]);
    }
}

// ---------------------------------------------------------------------------
// Kernel 3 (verbatim, frozen at its floor): fp16 GEMM, mma.sync + ldmatrix,
// cp.async.bulk + mbarrier. CTA tile 128x256, 4-stage ring (192KB), 512
// threads, warps 2x8, warp tile 64x32. Grid (2, 256).
// ---------------------------------------------------------------------------
#define A_STAGE   16384
#define B_STAGE   32768
#define STAGE_SZ  (A_STAGE + B_STAGE)
#define NSTAGE    4
#define GEMM_SMEM (NSTAGE * STAGE_SZ)     // 192 KB dynamic
#define KCHUNKS   16

__global__ void __launch_bounds__(512) gemm(const float* __restrict__ bias,
                                            float* __restrict__ out) {
    extern __shared__ __align__(1024) char dsm[];
    __shared__ __align__(16) uint64_t mbar[NSTAGE];

    const int t    = threadIdx.x;
    const int lane = t & 31;
    const int warp = t >> 5;
    const int wm   = warp >> 3;     // 0..1
    const int wn   = warp & 7;      // 0..7
    const int bx   = blockIdx.x;    // N block (0..1)
    const int by   = blockIdx.y;    // M block (0..255)

    const uint32_t smem_base = smem_u32(dsm);
    uint32_t mb[NSTAGE];
#pragma unroll
    for (int i = 0; i < NSTAGE; i++) mb[i] = smem_u32(&mbar[i]);

    const char* Abase = (const char*)g_A + (size_t)by * 16 * 16384;
    const char* Bbase = (const char*)g_W + (size_t)bx * 16 * 32768;

    if (t == 0) {
#pragma unroll
        for (int i = 0; i < NSTAGE; i++) MBARRIER_INIT(mb[i], 1);
        asm volatile("fence.proxy.async.shared::cta;" ::: "memory");
    }
    __syncthreads();

    auto issue = [&](int kc) {
        const int s = kc & (NSTAGE - 1);
        const uint32_t sa = smem_base + s * STAGE_SZ;
        MBARRIER_EXPECT_TX(mb[s], STAGE_SZ);
        bulk_g2s(sa,           Abase + (size_t)kc * A_STAGE, A_STAGE, mb[s]);
        bulk_g2s(sa + A_STAGE, Bbase + (size_t)kc * B_STAGE, B_STAGE, mb[s]);
    };

    if (t == 0) { issue(0); issue(1); issue(2); issue(3); }

    float c[4][2][2][4];
#pragma unroll
    for (int i = 0; i < 4; i++)
#pragma unroll
        for (int j = 0; j < 2; j++)
#pragma unroll
            for (int k = 0; k < 2; k++)
#pragma unroll
                for (int l = 0; l < 4; l++) c[i][j][k][l] = 0.0f;

    // ldmatrix per-lane address components (within a stage)
    const int rm     = lane & 7;
    const int a_roff = (wm * 64 + (lane & 15)) * 128;                      // + mt*2048
    const int a_m    = lane >> 4;
    const int b_roff = (wn * 32 + ((lane >> 4) << 3) + (lane & 7)) * 128;  // + p*2048
    const int b_m    = (lane >> 3) & 1;

    for (int kc = 0; kc < KCHUNKS; kc++) {
        const int st = kc & (NSTAGE - 1);
        MBARRIER_WAIT_PARITY(mb[st], (kc >> 2) & 1);

        const uint32_t sa = smem_base + st * STAGE_SZ;
        const uint32_t sb = sa + A_STAGE;

#pragma unroll
        for (int ks = 0; ks < 4; ks++) {                      // k16 steps
            uint32_t a[4][4], bf[2][4];
#pragma unroll
            for (int mt = 0; mt < 4; mt++)
                ldsm_x4(a[mt], sa + a_roff + mt * 2048 +
                               (((2 * ks + a_m) ^ rm) << 4));
#pragma unroll
            for (int p = 0; p < 2; p++)
                ldsm_x4(bf[p], sb + b_roff + p * 2048 +
                               (((2 * ks + b_m) ^ rm) << 4));
#pragma unroll
            for (int mt = 0; mt < 4; mt++)
#pragma unroll
                for (int p = 0; p < 2; p++) {
                    mma_f16(c[mt][p][0], a[mt], bf[p][0], bf[p][1]);
                    mma_f16(c[mt][p][1], a[mt], bf[p][2], bf[p][3]);
                }
        }

        __syncthreads();                    // all warps done reading stage st
        if (t == 0 && kc + NSTAGE < KCHUNKS) issue(kc + NSTAGE);
    }

    // epilogue: += bias, write fp32
#pragma unroll
    for (int p = 0; p < 2; p++)
#pragma unroll
        for (int ns = 0; ns < 2; ns++) {
            const int col = bx * 256 + wn * 32 + p * 16 + ns * 8 + 2 * (lane & 3);
            const float b0 = bias[col], b1 = bias[col + 1];
#pragma unroll
            for (int mt = 0; mt < 4; mt++) {
                const int r0 = by * 128 + wm * 64 + mt * 16 + (lane >> 2);
                float2 v0 = make_float2(c[mt][p][ns][0] + b0, c[mt][p][ns][1] + b1);
                float2 v1 = make_float2(c[mt][p][ns][2] + b0, c[mt][p][ns][3] + b1);
                *reinterpret_cast<float2*>(&out[(size_t)r0 * NTOT + col])       = v0;
                *reinterpret_cast<float2*>(&out[(size_t)(r0 + 8) * NTOT + col]) = v1;
            }
        }
}

// ---------------------------------------------------------------------------
extern "C" void kernel_launch(void* const* d_in, const int* in_sizes, int n_in,
                              void* d_out, int out_size) {
    const float* images = (const float*)d_in[0];
    const float* conv_w = (const float*)d_in[1];
    const float* conv_b = (const float*)d_in[2];
    const float* lin_w  = (const float*)d_in[3];
    const float* lin_b  = (const float*)d_in[4];
    float* out = (float*)d_out;

    cudaFuncSetAttribute(gemm, cudaFuncAttributeMaxDynamicSharedMemorySize,
                         GEMM_SMEM);

    abuild<<<dim3(2, 16, IMG_B), 512>>>(images, conv_w, conv_b);
    prepw<<<dim3(NTOT / 32, KTOT / 32), 256>>>(lin_w);
    gemm<<<dim3(NTOT / 256, MTOT / 128), 512, GEMM_SMEM>>>(lin_b, out);
}